// round 8
// baseline (speedup 1.0000x reference)
#include <cuda_runtime.h>
#include <cuda_bf16.h>
#include <mma.h>
#include <cstdint>

using namespace nvcuda;

#define NN 50000
#define EE 800000
#define CC 64
#define BN_EPS 1e-5f

// ---------------- scratch (static __device__ globals; no allocation) ----------------
static __device__ __align__(16) float g_P[NN * CC];      // x @ W0[:64]
static __device__ __align__(16) float g_Q[NN * CC];      // x @ W0[64:]
static __device__ __align__(16) float g_Y[EE * CC];      // y1 scratch (pre-BN layer1 output)
static __device__ int   g_src[EE];
static __device__ int   g_dst[EE];
static __device__ int   g_deg[NN];
static __device__ int   g_off[NN + 1];
static __device__ int   g_cur[NN];
static __device__ int   g_eperm[EE];
static __device__ __align__(16) float g_sum[3][CC];
static __device__ __align__(16) float g_sq[3][CC];
static __device__ __align__(16) float g_bnA[3][CC];
static __device__ __align__(16) float g_bnB[3][CC];
static __device__ int   g_is64;
// bf16 hi/lo split of W1/W2 (row-major [k][n])
static __device__ __align__(16) __nv_bfloat16 g_Whi[2][4096];
static __device__ __align__(16) __nv_bfloat16 g_Wlo[2][4096];

// ---------------- smem layout for wmma layer kernel (bytes) ----------------
#define LDA 72          // bf16 elements per A row (padded)
#define LDB 72          // bf16 elements per B row (padded)
#define LDS_F 68        // fp32 elements per stage row (padded)
#define O_AHI 0
#define O_ALO 18432     // 128*72*2
#define O_BHI 36864
#define O_BLO 46080     // +64*72*2
#define SMEM_LK 55296

// ---------------- prologue kernels ----------------

__global__ void k_zero() {
    int i = blockIdx.x * 256 + threadIdx.x;
    if (i < NN) g_deg[i] = 0;
    if (i < 3 * CC) {
        ((float*)g_sum)[i] = 0.0f;
        ((float*)g_sq)[i] = 0.0f;
    }
}

__global__ void k_detect(const unsigned* __restrict__ w) {
    __shared__ int bad;
    if (threadIdx.x == 0) bad = 0;
    __syncthreads();
    int b = 0;
    for (int i = threadIdx.x; i < 1024; i += 256)
        if (w[2 * i + 1] != 0u) b = 1;
    if (b) atomicOr(&bad, 1);
    __syncthreads();
    if (threadIdx.x == 0) g_is64 = bad ? 0 : 1;
}

__global__ void k_convert(const void* __restrict__ ei) {
    int e = blockIdx.x * 256 + threadIdx.x;
    if (e >= EE) return;
    int s, d;
    if (g_is64) {
        const long long* p = (const long long*)ei;
        s = (int)p[e];
        d = (int)p[EE + e];
    } else {
        const int* p = (const int*)ei;
        s = p[e];
        d = p[EE + e];
    }
    g_src[e] = s;
    g_dst[e] = d;
    atomicAdd(&g_deg[d], 1);
}

// single-block scan over degrees -> segment offsets (+ cursor copies)
__global__ void k_scan() {
    __shared__ int part[1024];
    int t = threadIdx.x;
    const int CH = (NN + 1023) / 1024;   // 49
    int base = t * CH;
    int s = 0;
    for (int j = 0; j < CH; j++) {
        int n = base + j;
        if (n < NN) s += g_deg[n];
    }
    part[t] = s;
    __syncthreads();
    for (int off = 1; off < 1024; off <<= 1) {
        int v = (t >= off) ? part[t - off] : 0;
        __syncthreads();
        part[t] += v;
        __syncthreads();
    }
    int run = part[t] - s;   // exclusive prefix for this chunk
    for (int j = 0; j < CH; j++) {
        int n = base + j;
        if (n < NN) {
            g_off[n] = run;
            g_cur[n] = run;
            run += g_deg[n];
        }
    }
    if (t == 1023) g_off[NN] = EE;
}

__global__ void k_sortE() {
    int e = blockIdx.x * 256 + threadIdx.x;
    if (e >= EE) return;
    int d = g_dst[e];
    int pos = atomicAdd(&g_cur[d], 1);
    g_eperm[pos] = e;
}

// Node-level GEMM: P = x @ W0[:64], Q = x @ W0[64:].
__global__ void __launch_bounds__(256) k_node(const float* __restrict__ x,
                                              const float* __restrict__ W0) {
    __shared__ float sW[64][128];
    __shared__ float sx[32][64];
    int t = threadIdx.x;
#pragma unroll
    for (int i = 0; i < 32; i++) {
        int idx = t + i * 256;
        int k = idx >> 7;
        int cc = idx & 127;
        sW[k][cc] = (cc < 64) ? W0[k * 64 + cc] : W0[(64 + k) * 64 + (cc - 64)];
    }
    int n0 = blockIdx.x * 32;
#pragma unroll
    for (int i = 0; i < 8; i++) {
        int idx = t + i * 256;
        int nl = idx >> 6;
        int k = idx & 63;
        int n = n0 + nl;
        sx[nl][k] = (n < NN) ? x[n * 64 + k] : 0.0f;
    }
    __syncthreads();
    int tc = t & 31;
    int tn = t >> 5;
    float acc[4][4] = {};
#pragma unroll 16
    for (int k = 0; k < 64; k++) {
        float4 w = *(const float4*)&sW[k][tc * 4];
        float x0 = sx[tn * 4 + 0][k];
        float x1 = sx[tn * 4 + 1][k];
        float x2 = sx[tn * 4 + 2][k];
        float x3 = sx[tn * 4 + 3][k];
        acc[0][0] = fmaf(x0, w.x, acc[0][0]); acc[0][1] = fmaf(x0, w.y, acc[0][1]);
        acc[0][2] = fmaf(x0, w.z, acc[0][2]); acc[0][3] = fmaf(x0, w.w, acc[0][3]);
        acc[1][0] = fmaf(x1, w.x, acc[1][0]); acc[1][1] = fmaf(x1, w.y, acc[1][1]);
        acc[1][2] = fmaf(x1, w.z, acc[1][2]); acc[1][3] = fmaf(x1, w.w, acc[1][3]);
        acc[2][0] = fmaf(x2, w.x, acc[2][0]); acc[2][1] = fmaf(x2, w.y, acc[2][1]);
        acc[2][2] = fmaf(x2, w.z, acc[2][2]); acc[2][3] = fmaf(x2, w.w, acc[2][3]);
        acc[3][0] = fmaf(x3, w.x, acc[3][0]); acc[3][1] = fmaf(x3, w.y, acc[3][1]);
        acc[3][2] = fmaf(x3, w.z, acc[3][2]); acc[3][3] = fmaf(x3, w.w, acc[3][3]);
    }
#pragma unroll
    for (int i = 0; i < 4; i++) {
        int n = n0 + tn * 4 + i;
        if (n < NN) {
            float4 v = make_float4(acc[i][0], acc[i][1], acc[i][2], acc[i][3]);
            if (tc < 16)
                *(float4*)&g_P[n * 64 + tc * 4] = v;
            else
                *(float4*)&g_Q[n * 64 + (tc - 16) * 4] = v;
        }
    }
}

__global__ void k_stats0() {
    __shared__ float ss[CC], sq[CC];
    int t = threadIdx.x;
    if (t < CC) { ss[t] = 0.0f; sq[t] = 0.0f; }
    __syncthreads();
    int lane = t & 31;
    int warp = (blockIdx.x * 256 + t) >> 5;
    int nw = (gridDim.x * 256) >> 5;
    float2 s = make_float2(0.0f, 0.0f), q = make_float2(0.0f, 0.0f);
    for (int e = warp; e < EE; e += nw) {
        int dst = g_dst[e], src = g_src[e];
        float2 p = *(const float2*)&g_P[dst * CC + 2 * lane];
        float2 qq = *(const float2*)&g_Q[src * CC + 2 * lane];
        float y0 = p.x + qq.x, y1 = p.y + qq.y;
        s.x += y0; s.y += y1;
        q.x = fmaf(y0, y0, q.x); q.y = fmaf(y1, y1, q.y);
    }
    atomicAdd(&ss[2 * lane], s.x);
    atomicAdd(&ss[2 * lane + 1], s.y);
    atomicAdd(&sq[2 * lane], q.x);
    atomicAdd(&sq[2 * lane + 1], q.y);
    __syncthreads();
    if (t < CC) {
        atomicAdd(&g_sum[0][t], ss[t]);
        atomicAdd(&g_sq[0][t], sq[t]);
    }
}

__global__ void k_finalize(int layer, const float* __restrict__ gam,
                           const float* __restrict__ bet) {
    int c = threadIdx.x;
    float inv = 1.0f / (float)EE;
    float m = g_sum[layer][c] * inv;
    float v = g_sq[layer][c] * inv - m * m;
    float a = gam[c] * rsqrtf(v + BN_EPS);
    g_bnA[layer][c] = a;
    g_bnB[layer][c] = bet[c] - m * a;
}

// Prologue: bf16 hi/lo split of W1, W2 (row-major [k][n]).
__global__ void k_prepW(const float* __restrict__ W1, const float* __restrict__ W2) {
    const float* W = (blockIdx.x == 0) ? W1 : W2;
    for (int idx = threadIdx.x; idx < 4096; idx += 256) {
        float x = W[idx];
        __nv_bfloat16 hi = __float2bfloat16(x);
        __nv_bfloat16 lo = __float2bfloat16(x - __bfloat162float(hi));
        g_Whi[blockIdx.x][idx] = hi;
        g_Wlo[blockIdx.x][idx] = lo;
    }
}

// ---------------- WMMA edge layer (shared by layer1 & layer2) ----------------
// mode 0: A = BN0+ReLU(P[dst]+Q[src]), B = W1, out -> g_Y,  stats -> 1
// mode 1: A = BN1+ReLU(g_Y),           B = W2, out -> outE, stats -> 2
// y = Ahi*Bhi + Alo*Bhi + Ahi*Blo (fp32 accum), error ~2^-17 relative.
__global__ void __launch_bounds__(256) k_layerT(int mode, float* __restrict__ outE) {
    extern __shared__ char smem[];
    __nv_bfloat16* A_hi = (__nv_bfloat16*)(smem + O_AHI);
    __nv_bfloat16* A_lo = (__nv_bfloat16*)(smem + O_ALO);
    __nv_bfloat16* B_hi = (__nv_bfloat16*)(smem + O_BHI);
    __nv_bfloat16* B_lo = (__nv_bfloat16*)(smem + O_BLO);
    float* stage = (float*)smem;   // reuses A region after compute
    int t = threadIdx.x;

    // copy W hi/lo into padded smem (row k -> B[k*LDB .. +64))
    {
        const uint32_t* wh = (const uint32_t*)&g_Whi[mode][0];
        const uint32_t* wl = (const uint32_t*)&g_Wlo[mode][0];
#pragma unroll
        for (int i = 0; i < 8; i++) {
            int idx2 = t + i * 256;          // pair index, 0..2047
            int k = idx2 >> 5, n2 = idx2 & 31;
            ((uint32_t*)(B_hi + k * LDB))[n2] = wh[idx2];
            ((uint32_t*)(B_lo + k * LDB))[n2] = wl[idx2];
        }
    }

    // A fill: 2 threads per edge row (32 cols each), BN+ReLU+split -> bf16 hi/lo
    int e0 = blockIdx.x * 128;
    int r = t >> 1, half = t & 1;
    int e = e0 + r;
    const float* src0;
    const float* src1 = nullptr;
    int L;
    if (mode == 0) {
        src0 = &g_P[(size_t)g_dst[e] * CC];
        src1 = &g_Q[(size_t)g_src[e] * CC];
        L = 0;
    } else {
        src0 = &g_Y[(size_t)e * CC];
        L = 1;
    }
    int cbase = half * 32;
#pragma unroll
    for (int i = 0; i < 4; i++) {
        int c = cbase + i * 8;
        float4 a0 = *(const float4*)&src0[c];
        float4 a1 = *(const float4*)&src0[c + 4];
        if (mode == 0) {
            float4 b0 = *(const float4*)&src1[c];
            float4 b1 = *(const float4*)&src1[c + 4];
            a0.x += b0.x; a0.y += b0.y; a0.z += b0.z; a0.w += b0.w;
            a1.x += b1.x; a1.y += b1.y; a1.z += b1.z; a1.w += b1.w;
        }
        float v[8] = {a0.x, a0.y, a0.z, a0.w, a1.x, a1.y, a1.z, a1.w};
        float4 A0 = *(const float4*)&g_bnA[L][c];
        float4 A1 = *(const float4*)&g_bnA[L][c + 4];
        float4 B0 = *(const float4*)&g_bnB[L][c];
        float4 B1 = *(const float4*)&g_bnB[L][c + 4];
        float bnA[8] = {A0.x, A0.y, A0.z, A0.w, A1.x, A1.y, A1.z, A1.w};
        float bnB[8] = {B0.x, B0.y, B0.z, B0.w, B1.x, B1.y, B1.z, B1.w};
        uint32_t hw[4], lw[4];
#pragma unroll
        for (int j = 0; j < 4; j++) {
            float x0 = fmaxf(fmaf(bnA[2 * j],     v[2 * j],     bnB[2 * j]),     0.0f);
            float x1 = fmaxf(fmaf(bnA[2 * j + 1], v[2 * j + 1], bnB[2 * j + 1]), 0.0f);
            __nv_bfloat16 h0 = __float2bfloat16(x0);
            __nv_bfloat16 h1 = __float2bfloat16(x1);
            __nv_bfloat16 l0 = __float2bfloat16(x0 - __bfloat162float(h0));
            __nv_bfloat16 l1 = __float2bfloat16(x1 - __bfloat162float(h1));
            hw[j] = (uint32_t)__bfloat16_as_ushort(h0) |
                    ((uint32_t)__bfloat16_as_ushort(h1) << 16);
            lw[j] = (uint32_t)__bfloat16_as_ushort(l0) |
                    ((uint32_t)__bfloat16_as_ushort(l1) << 16);
        }
        *(uint4*)&A_hi[r * LDA + c] = make_uint4(hw[0], hw[1], hw[2], hw[3]);
        *(uint4*)&A_lo[r * LDA + c] = make_uint4(lw[0], lw[1], lw[2], lw[3]);
    }
    __syncthreads();

    // WMMA: warp w -> rows [w*16, w*16+16), all 64 cols
    int w = t >> 5;
    int row0 = w * 16;
    wmma::fragment<wmma::accumulator, 16, 16, 16, float> acc[4];
#pragma unroll
    for (int j = 0; j < 4; j++) wmma::fill_fragment(acc[j], 0.0f);
#pragma unroll
    for (int k0 = 0; k0 < 64; k0 += 16) {
        wmma::fragment<wmma::matrix_a, 16, 16, 16, __nv_bfloat16, wmma::row_major> ah, al;
        wmma::load_matrix_sync(ah, A_hi + row0 * LDA + k0, LDA);
        wmma::load_matrix_sync(al, A_lo + row0 * LDA + k0, LDA);
#pragma unroll
        for (int j = 0; j < 4; j++) {
            wmma::fragment<wmma::matrix_b, 16, 16, 16, __nv_bfloat16, wmma::row_major> bh, bl;
            wmma::load_matrix_sync(bh, B_hi + k0 * LDB + j * 16, LDB);
            wmma::load_matrix_sync(bl, B_lo + k0 * LDB + j * 16, LDB);
            wmma::mma_sync(acc[j], ah, bh, acc[j]);
            wmma::mma_sync(acc[j], al, bh, acc[j]);
            wmma::mma_sync(acc[j], ah, bl, acc[j]);
        }
    }
    __syncthreads();   // everyone done reading A region before stage overwrite
#pragma unroll
    for (int j = 0; j < 4; j++)
        wmma::store_matrix_sync(stage + row0 * LDS_F + j * 16, acc[j], LDS_F,
                                wmma::mem_row_major);
    __syncthreads();

    // column stats: 256 threads, c = t&63, quarter sums 32 rows
    {
        int c = t & 63, quarter = t >> 6;
        float s = 0.0f, q = 0.0f;
#pragma unroll 8
        for (int rr = 0; rr < 32; rr++) {
            float vv = stage[(quarter * 32 + rr) * LDS_F + c];
            s += vv;
            q = fmaf(vv, vv, q);
        }
        int SL = (mode == 0) ? 1 : 2;
        atomicAdd(&g_sum[SL][c], s);
        atomicAdd(&g_sq[SL][c], q);
    }

    // coalesced store of the 128x64 tile
    float* dst = (mode == 0) ? (g_Y + (size_t)e0 * CC) : (outE + (size_t)e0 * CC);
#pragma unroll
    for (int j2 = 0; j2 < 8; j2++) {
        int f = j2 * 1024 + t * 4;
        int rr = f >> 6, cc2 = f & 63;
        uint4 v = *(const uint4*)&stage[rr * LDS_F + cc2];
        *(uint4*)&dst[f] = v;
    }
}

// Segmented mean: warp per node. Applies BN2+ReLU to each of its edges' rows
// (in place in the output edge region) and writes the node mean. No atomics.
__global__ void __launch_bounds__(256) k_agg(float* __restrict__ out) {
    int wid = (blockIdx.x * 256 + threadIdx.x) >> 5;
    int lane = threadIdx.x & 31;
    if (wid >= NN) return;
    int start = g_off[wid], end = g_off[wid + 1];
    float2 A = *(const float2*)&g_bnA[2][lane * 2];
    float2 Bv = *(const float2*)&g_bnB[2][lane * 2];
    float2 acc = make_float2(0.0f, 0.0f);
    float* oe = out + (size_t)NN * CC;
    for (int j = start; j < end; j++) {
        int eid = g_eperm[j];
        float* row = oe + (size_t)eid * CC + lane * 2;
        float2 v = *(float2*)row;
        v.x = fmaxf(fmaf(A.x, v.x, Bv.x), 0.0f);
        v.y = fmaxf(fmaf(A.y, v.y, Bv.y), 0.0f);
        *(float2*)row = v;
        acc.x += v.x;
        acc.y += v.y;
    }
    float d = fmaxf((float)(end - start), 1.0f);
    acc.x /= d;
    acc.y /= d;
    *(float2*)&out[(size_t)wid * CC + lane * 2] = acc;
}

extern "C" void kernel_launch(void* const* d_in, const int* in_sizes, int n_in,
                              void* d_out, int out_size) {
    const float* x = (const float*)d_in[0];
    const void* ei = d_in[1];
    const float* W0 = (const float*)d_in[2];
    const float* g0 = (const float*)d_in[4];
    const float* be0 = (const float*)d_in[5];
    const float* W1 = (const float*)d_in[6];
    const float* g1 = (const float*)d_in[8];
    const float* be1 = (const float*)d_in[9];
    const float* W2 = (const float*)d_in[10];
    const float* g2 = (const float*)d_in[12];
    const float* be2 = (const float*)d_in[13];
    float* out = (float*)d_out;
    float* outE = out + NN * CC;

    static int s_attr_done = 0;
    if (!s_attr_done) {
        cudaFuncSetAttribute(k_layerT, cudaFuncAttributeMaxDynamicSharedMemorySize, SMEM_LK);
        s_attr_done = 1;
    }

    k_zero<<<(NN + 255) / 256, 256>>>();
    k_detect<<<1, 256>>>((const unsigned*)ei);
    k_convert<<<(EE + 255) / 256, 256>>>(ei);
    k_prepW<<<2, 256>>>(W1, W2);
    k_node<<<(NN + 31) / 32, 256>>>(x, W0);
    k_scan<<<1, 1024>>>();
    k_sortE<<<(EE + 255) / 256, 256>>>();
    k_stats0<<<2048, 256>>>();
    k_finalize<<<1, 64>>>(0, g0, be0);
    k_layerT<<<EE / 128, 256, SMEM_LK>>>(0, outE);
    k_finalize<<<1, 64>>>(1, g1, be1);
    k_layerT<<<EE / 128, 256, SMEM_LK>>>(1, outE);
    k_finalize<<<1, 64>>>(2, g2, be2);
    k_agg<<<(NN * 32 + 255) / 256, 256>>>(out);
}

// round 9
// speedup vs baseline: 1.0630x; 1.0630x over previous
#include <cuda_runtime.h>
#include <cuda_bf16.h>
#include <mma.h>
#include <cstdint>

using namespace nvcuda;

#define NN 50000
#define EE 800000
#define CC 64
#define BN_EPS 1e-5f

// ---------------- scratch (static __device__ globals; no allocation) ----------------
static __device__ __align__(16) float g_P[NN * CC];      // x @ W0[:64]
static __device__ __align__(16) float g_Q[NN * CC];      // x @ W0[64:]
static __device__ __align__(16) float g_Y[EE * CC];      // sorted-order y scratch
static __device__ int   g_src[EE];
static __device__ int   g_dst[EE];
static __device__ int   g_ssrc[EE];                      // src of sorted edge
static __device__ int   g_sdst[EE];                      // dst of sorted edge
static __device__ int   g_deg[NN];
static __device__ int   g_off[NN + 1];
static __device__ int   g_cur[NN];
static __device__ int   g_eperm[EE];                     // sorted pos -> original edge id
static __device__ __align__(16) float g_sum[3][CC];
static __device__ __align__(16) float g_sq[3][CC];
static __device__ __align__(16) float g_bnA[3][CC];
static __device__ __align__(16) float g_bnB[3][CC];
static __device__ int   g_is64;
// bf16 hi/lo split of W1/W2 (row-major [k][n])
static __device__ __align__(16) __nv_bfloat16 g_Whi[2][4096];
static __device__ __align__(16) __nv_bfloat16 g_Wlo[2][4096];

// ---------------- smem layout for wmma layer kernel (bytes) ----------------
#define LDA 72          // bf16 elements per A row (padded)
#define LDB 72          // bf16 elements per B row (padded)
#define LDS_F 68        // fp32 elements per stage row (padded)
#define O_AHI 0
#define O_ALO 18432     // 128*72*2
#define O_BHI 36864
#define O_BLO 46080     // +64*72*2
#define SMEM_LK 55296

// ---------------- prologue kernels ----------------

__global__ void k_zero() {
    int i = blockIdx.x * 256 + threadIdx.x;
    if (i < NN) g_deg[i] = 0;
    if (i < 3 * CC) {
        ((float*)g_sum)[i] = 0.0f;
        ((float*)g_sq)[i] = 0.0f;
    }
}

__global__ void k_detect(const unsigned* __restrict__ w) {
    __shared__ int bad;
    if (threadIdx.x == 0) bad = 0;
    __syncthreads();
    int b = 0;
    for (int i = threadIdx.x; i < 1024; i += 256)
        if (w[2 * i + 1] != 0u) b = 1;
    if (b) atomicOr(&bad, 1);
    __syncthreads();
    if (threadIdx.x == 0) g_is64 = bad ? 0 : 1;
}

__global__ void k_convert(const void* __restrict__ ei) {
    int e = blockIdx.x * 256 + threadIdx.x;
    if (e >= EE) return;
    int s, d;
    if (g_is64) {
        const long long* p = (const long long*)ei;
        s = (int)p[e];
        d = (int)p[EE + e];
    } else {
        const int* p = (const int*)ei;
        s = p[e];
        d = p[EE + e];
    }
    g_src[e] = s;
    g_dst[e] = d;
    atomicAdd(&g_deg[d], 1);
}

// single-block scan over degrees -> segment offsets (+ cursor copies)
__global__ void k_scan() {
    __shared__ int part[1024];
    int t = threadIdx.x;
    const int CH = (NN + 1023) / 1024;   // 49
    int base = t * CH;
    int s = 0;
    for (int j = 0; j < CH; j++) {
        int n = base + j;
        if (n < NN) s += g_deg[n];
    }
    part[t] = s;
    __syncthreads();
    for (int off = 1; off < 1024; off <<= 1) {
        int v = (t >= off) ? part[t - off] : 0;
        __syncthreads();
        part[t] += v;
        __syncthreads();
    }
    int run = part[t] - s;   // exclusive prefix for this chunk
    for (int j = 0; j < CH; j++) {
        int n = base + j;
        if (n < NN) {
            g_off[n] = run;
            g_cur[n] = run;
            run += g_deg[n];
        }
    }
    if (t == 1023) g_off[NN] = EE;
}

__global__ void k_sortE() {
    int e = blockIdx.x * 256 + threadIdx.x;
    if (e >= EE) return;
    int s = g_src[e];
    int d = g_dst[e];
    int pos = atomicAdd(&g_cur[d], 1);
    g_eperm[pos] = e;
    g_ssrc[pos] = s;
    g_sdst[pos] = d;
}

// Node-level GEMM: P = x @ W0[:64], Q = x @ W0[64:].
__global__ void __launch_bounds__(256) k_node(const float* __restrict__ x,
                                              const float* __restrict__ W0) {
    __shared__ float sW[64][128];
    __shared__ float sx[32][64];
    int t = threadIdx.x;
#pragma unroll
    for (int i = 0; i < 32; i++) {
        int idx = t + i * 256;
        int k = idx >> 7;
        int cc = idx & 127;
        sW[k][cc] = (cc < 64) ? W0[k * 64 + cc] : W0[(64 + k) * 64 + (cc - 64)];
    }
    int n0 = blockIdx.x * 32;
#pragma unroll
    for (int i = 0; i < 8; i++) {
        int idx = t + i * 256;
        int nl = idx >> 6;
        int k = idx & 63;
        int n = n0 + nl;
        sx[nl][k] = (n < NN) ? x[n * 64 + k] : 0.0f;
    }
    __syncthreads();
    int tc = t & 31;
    int tn = t >> 5;
    float acc[4][4] = {};
#pragma unroll 16
    for (int k = 0; k < 64; k++) {
        float4 w = *(const float4*)&sW[k][tc * 4];
        float x0 = sx[tn * 4 + 0][k];
        float x1 = sx[tn * 4 + 1][k];
        float x2 = sx[tn * 4 + 2][k];
        float x3 = sx[tn * 4 + 3][k];
        acc[0][0] = fmaf(x0, w.x, acc[0][0]); acc[0][1] = fmaf(x0, w.y, acc[0][1]);
        acc[0][2] = fmaf(x0, w.z, acc[0][2]); acc[0][3] = fmaf(x0, w.w, acc[0][3]);
        acc[1][0] = fmaf(x1, w.x, acc[1][0]); acc[1][1] = fmaf(x1, w.y, acc[1][1]);
        acc[1][2] = fmaf(x1, w.z, acc[1][2]); acc[1][3] = fmaf(x1, w.w, acc[1][3]);
        acc[2][0] = fmaf(x2, w.x, acc[2][0]); acc[2][1] = fmaf(x2, w.y, acc[2][1]);
        acc[2][2] = fmaf(x2, w.z, acc[2][2]); acc[2][3] = fmaf(x2, w.w, acc[2][3]);
        acc[3][0] = fmaf(x3, w.x, acc[3][0]); acc[3][1] = fmaf(x3, w.y, acc[3][1]);
        acc[3][2] = fmaf(x3, w.z, acc[3][2]); acc[3][3] = fmaf(x3, w.w, acc[3][3]);
    }
#pragma unroll
    for (int i = 0; i < 4; i++) {
        int n = n0 + tn * 4 + i;
        if (n < NN) {
            float4 v = make_float4(acc[i][0], acc[i][1], acc[i][2], acc[i][3]);
            if (tc < 16)
                *(float4*)&g_P[n * 64 + tc * 4] = v;
            else
                *(float4*)&g_Q[n * 64 + (tc - 16) * 4] = v;
        }
    }
}

// Layer-0 stats over sorted pairs (dst-sorted -> P rows L1-resident).
__global__ void k_stats0() {
    __shared__ float ss[CC], sq[CC];
    int t = threadIdx.x;
    if (t < CC) { ss[t] = 0.0f; sq[t] = 0.0f; }
    __syncthreads();
    int lane = t & 31;
    int warp = (blockIdx.x * 256 + t) >> 5;
    int nw = (gridDim.x * 256) >> 5;
    float2 s = make_float2(0.0f, 0.0f), q = make_float2(0.0f, 0.0f);
    for (int e = warp; e < EE; e += nw) {
        int dst = g_sdst[e], src = g_ssrc[e];
        float2 p = *(const float2*)&g_P[dst * CC + 2 * lane];
        float2 qq = *(const float2*)&g_Q[src * CC + 2 * lane];
        float y0 = p.x + qq.x, y1 = p.y + qq.y;
        s.x += y0; s.y += y1;
        q.x = fmaf(y0, y0, q.x); q.y = fmaf(y1, y1, q.y);
    }
    atomicAdd(&ss[2 * lane], s.x);
    atomicAdd(&ss[2 * lane + 1], s.y);
    atomicAdd(&sq[2 * lane], q.x);
    atomicAdd(&sq[2 * lane + 1], q.y);
    __syncthreads();
    if (t < CC) {
        atomicAdd(&g_sum[0][t], ss[t]);
        atomicAdd(&g_sq[0][t], sq[t]);
    }
}

__global__ void k_finalize(int layer, const float* __restrict__ gam,
                           const float* __restrict__ bet) {
    int c = threadIdx.x;
    float inv = 1.0f / (float)EE;
    float m = g_sum[layer][c] * inv;
    float v = g_sq[layer][c] * inv - m * m;
    float a = gam[c] * rsqrtf(v + BN_EPS);
    g_bnA[layer][c] = a;
    g_bnB[layer][c] = bet[c] - m * a;
}

// Prologue: bf16 hi/lo split of W1, W2 (row-major [k][n]).
__global__ void k_prepW(const float* __restrict__ W1, const float* __restrict__ W2) {
    const float* W = (blockIdx.x == 0) ? W1 : W2;
    for (int idx = threadIdx.x; idx < 4096; idx += 256) {
        float x = W[idx];
        __nv_bfloat16 hi = __float2bfloat16(x);
        __nv_bfloat16 lo = __float2bfloat16(x - __bfloat162float(hi));
        g_Whi[blockIdx.x][idx] = hi;
        g_Wlo[blockIdx.x][idx] = lo;
    }
}

// ---------------- WMMA edge layer, sorted-position order ----------------
// mode 0: A = BN0+ReLU(P[sdst]+Q[ssrc]), B = W1, g_Y[pos] = y1, stats -> 1
// mode 1: A = BN1+ReLU(g_Y[pos]),        B = W2, g_Y[pos] = y2, stats -> 2
// y = Ahi*Bhi + Alo*Bhi + Ahi*Blo (fp32 accum).
__global__ void __launch_bounds__(256) k_layerT(int mode) {
    extern __shared__ char smem[];
    __nv_bfloat16* A_hi = (__nv_bfloat16*)(smem + O_AHI);
    __nv_bfloat16* A_lo = (__nv_bfloat16*)(smem + O_ALO);
    __nv_bfloat16* B_hi = (__nv_bfloat16*)(smem + O_BHI);
    __nv_bfloat16* B_lo = (__nv_bfloat16*)(smem + O_BLO);
    float* stage = (float*)smem;   // reuses A region after compute
    int t = threadIdx.x;

    // copy W hi/lo into padded smem (row k -> B[k*LDB .. +64))
    {
        const uint32_t* wh = (const uint32_t*)&g_Whi[mode][0];
        const uint32_t* wl = (const uint32_t*)&g_Wlo[mode][0];
#pragma unroll
        for (int i = 0; i < 8; i++) {
            int idx2 = t + i * 256;          // pair index, 0..2047
            int k = idx2 >> 5, n2 = idx2 & 31;
            ((uint32_t*)(B_hi + k * LDB))[n2] = wh[idx2];
            ((uint32_t*)(B_lo + k * LDB))[n2] = wl[idx2];
        }
    }

    // A fill: 2 threads per sorted row (32 cols each), BN+ReLU+split -> bf16 hi/lo
    int e0 = blockIdx.x * 128;
    int r = t >> 1, half = t & 1;
    int pos = e0 + r;
    const float* src0;
    const float* src1 = nullptr;
    int L;
    if (mode == 0) {
        src0 = &g_P[(size_t)g_sdst[pos] * CC];
        src1 = &g_Q[(size_t)g_ssrc[pos] * CC];
        L = 0;
    } else {
        src0 = &g_Y[(size_t)pos * CC];
        L = 1;
    }
    int cbase = half * 32;
#pragma unroll
    for (int i = 0; i < 4; i++) {
        int c = cbase + i * 8;
        float4 a0 = *(const float4*)&src0[c];
        float4 a1 = *(const float4*)&src0[c + 4];
        if (mode == 0) {
            float4 b0 = *(const float4*)&src1[c];
            float4 b1 = *(const float4*)&src1[c + 4];
            a0.x += b0.x; a0.y += b0.y; a0.z += b0.z; a0.w += b0.w;
            a1.x += b1.x; a1.y += b1.y; a1.z += b1.z; a1.w += b1.w;
        }
        float v[8] = {a0.x, a0.y, a0.z, a0.w, a1.x, a1.y, a1.z, a1.w};
        float4 A0 = *(const float4*)&g_bnA[L][c];
        float4 A1 = *(const float4*)&g_bnA[L][c + 4];
        float4 B0 = *(const float4*)&g_bnB[L][c];
        float4 B1 = *(const float4*)&g_bnB[L][c + 4];
        float bnA[8] = {A0.x, A0.y, A0.z, A0.w, A1.x, A1.y, A1.z, A1.w};
        float bnB[8] = {B0.x, B0.y, B0.z, B0.w, B1.x, B1.y, B1.z, B1.w};
        uint32_t hw[4], lw[4];
#pragma unroll
        for (int j = 0; j < 4; j++) {
            float x0 = fmaxf(fmaf(bnA[2 * j],     v[2 * j],     bnB[2 * j]),     0.0f);
            float x1 = fmaxf(fmaf(bnA[2 * j + 1], v[2 * j + 1], bnB[2 * j + 1]), 0.0f);
            __nv_bfloat16 h0 = __float2bfloat16(x0);
            __nv_bfloat16 h1 = __float2bfloat16(x1);
            __nv_bfloat16 l0 = __float2bfloat16(x0 - __bfloat162float(h0));
            __nv_bfloat16 l1 = __float2bfloat16(x1 - __bfloat162float(h1));
            hw[j] = (uint32_t)__bfloat16_as_ushort(h0) |
                    ((uint32_t)__bfloat16_as_ushort(h1) << 16);
            lw[j] = (uint32_t)__bfloat16_as_ushort(l0) |
                    ((uint32_t)__bfloat16_as_ushort(l1) << 16);
        }
        *(uint4*)&A_hi[r * LDA + c] = make_uint4(hw[0], hw[1], hw[2], hw[3]);
        *(uint4*)&A_lo[r * LDA + c] = make_uint4(lw[0], lw[1], lw[2], lw[3]);
    }
    __syncthreads();

    // WMMA: warp w -> rows [w*16, w*16+16), all 64 cols
    int w = t >> 5;
    int row0 = w * 16;
    wmma::fragment<wmma::accumulator, 16, 16, 16, float> acc[4];
#pragma unroll
    for (int j = 0; j < 4; j++) wmma::fill_fragment(acc[j], 0.0f);
#pragma unroll
    for (int k0 = 0; k0 < 64; k0 += 16) {
        wmma::fragment<wmma::matrix_a, 16, 16, 16, __nv_bfloat16, wmma::row_major> ah, al;
        wmma::load_matrix_sync(ah, A_hi + row0 * LDA + k0, LDA);
        wmma::load_matrix_sync(al, A_lo + row0 * LDA + k0, LDA);
#pragma unroll
        for (int j = 0; j < 4; j++) {
            wmma::fragment<wmma::matrix_b, 16, 16, 16, __nv_bfloat16, wmma::row_major> bh, bl;
            wmma::load_matrix_sync(bh, B_hi + k0 * LDB + j * 16, LDB);
            wmma::load_matrix_sync(bl, B_lo + k0 * LDB + j * 16, LDB);
            wmma::mma_sync(acc[j], ah, bh, acc[j]);
            wmma::mma_sync(acc[j], al, bh, acc[j]);
            wmma::mma_sync(acc[j], ah, bl, acc[j]);
        }
    }
    __syncthreads();   // everyone done reading A region before stage overwrite
#pragma unroll
    for (int j = 0; j < 4; j++)
        wmma::store_matrix_sync(stage + row0 * LDS_F + j * 16, acc[j], LDS_F,
                                wmma::mem_row_major);
    __syncthreads();

    // column stats: 256 threads, c = t&63, quarter sums 32 rows
    {
        int c = t & 63, quarter = t >> 6;
        float s = 0.0f, q = 0.0f;
#pragma unroll 8
        for (int rr = 0; rr < 32; rr++) {
            float vv = stage[(quarter * 32 + rr) * LDS_F + c];
            s += vv;
            q = fmaf(vv, vv, q);
        }
        int SL = (mode == 0) ? 1 : 2;
        atomicAdd(&g_sum[SL][c], s);
        atomicAdd(&g_sq[SL][c], q);
    }

    // coalesced store of the 128x64 tile back to sorted scratch
    float* dst = g_Y + (size_t)e0 * CC;
#pragma unroll
    for (int j2 = 0; j2 < 8; j2++) {
        int f = j2 * 1024 + t * 4;
        int rr = f >> 6, cc2 = f & 63;
        uint4 v = *(const uint4*)&stage[rr * LDS_F + cc2];
        *(uint4*)&dst[f] = v;
    }
}

// Segmented mean: warp per node. Streams its CONTIGUOUS sorted g_Y segment
// (coalesced reads), applies BN2+ReLU, scatter-writes edge rows to outE in
// original order, accumulates and writes the node mean. No atomics.
__global__ void __launch_bounds__(256) k_agg(float* __restrict__ out) {
    int wid = (blockIdx.x * 256 + threadIdx.x) >> 5;
    int lane = threadIdx.x & 31;
    if (wid >= NN) return;
    int start = g_off[wid], end = g_off[wid + 1];
    float2 A = *(const float2*)&g_bnA[2][lane * 2];
    float2 Bv = *(const float2*)&g_bnB[2][lane * 2];
    float2 acc = make_float2(0.0f, 0.0f);
    float* oe = out + (size_t)NN * CC;
#pragma unroll 2
    for (int j = start; j < end; j++) {
        float2 v = *(const float2*)&g_Y[(size_t)j * CC + lane * 2];
        v.x = fmaxf(fmaf(A.x, v.x, Bv.x), 0.0f);
        v.y = fmaxf(fmaf(A.y, v.y, Bv.y), 0.0f);
        int eid = g_eperm[j];
        *(float2*)&oe[(size_t)eid * CC + lane * 2] = v;
        acc.x += v.x;
        acc.y += v.y;
    }
    float d = fmaxf((float)(end - start), 1.0f);
    *(float2*)&out[(size_t)wid * CC + lane * 2] =
        make_float2(acc.x / d, acc.y / d);
}

extern "C" void kernel_launch(void* const* d_in, const int* in_sizes, int n_in,
                              void* d_out, int out_size) {
    const float* x = (const float*)d_in[0];
    const void* ei = d_in[1];
    const float* W0 = (const float*)d_in[2];
    const float* g0 = (const float*)d_in[4];
    const float* be0 = (const float*)d_in[5];
    const float* W1 = (const float*)d_in[6];
    const float* g1 = (const float*)d_in[8];
    const float* be1 = (const float*)d_in[9];
    const float* W2 = (const float*)d_in[10];
    const float* g2 = (const float*)d_in[12];
    const float* be2 = (const float*)d_in[13];
    float* out = (float*)d_out;

    static int s_attr_done = 0;
    if (!s_attr_done) {
        cudaFuncSetAttribute(k_layerT, cudaFuncAttributeMaxDynamicSharedMemorySize, SMEM_LK);
        s_attr_done = 1;
    }

    k_zero<<<(NN + 255) / 256, 256>>>();
    k_detect<<<1, 256>>>((const unsigned*)ei);
    k_convert<<<(EE + 255) / 256, 256>>>(ei);
    k_node<<<(NN + 31) / 32, 256>>>(x, W0);
    k_scan<<<1, 1024>>>();
    k_sortE<<<(EE + 255) / 256, 256>>>();
    k_prepW<<<2, 256>>>(W1, W2);
    k_stats0<<<2048, 256>>>();
    k_finalize<<<1, 64>>>(0, g0, be0);
    k_layerT<<<EE / 128, 256, SMEM_LK>>>(0);
    k_finalize<<<1, 64>>>(1, g1, be1);
    k_layerT<<<EE / 128, 256, SMEM_LK>>>(1);
    k_finalize<<<1, 64>>>(2, g2, be2);
    k_agg<<<(NN * 32 + 255) / 256, 256>>>(out);
}